// round 5
// baseline (speedup 1.0000x reference)
#include <cuda_runtime.h>
#include <math.h>

#define EPS 1e-8f
#define LN_EPS 1e-5f
#define CHUNK 32

// ---------------- scratch (static __device__, no allocs) ----------------
__device__ float  g_q[16*512*64];
__device__ float  g_z[16*512*64];
__device__ float  g_v[16*512*64];
__device__ float  g_rqn[16*512];
__device__ float  g_part[16*16*4160];
__device__ float  g_base[16*16*4160];
__device__ float4 g_pack[16*4096];      // {sg, sb+Ps_ln, ng, nb+Mprev_ln}
__device__ float  g_Pz[16*64];          // P_z_ln last step per batch
__device__ double g_acc[2];             // sum, sumsq for std

__device__ __forceinline__ float eluf(float x){ return x > 0.f ? x : (expf(x) - 1.f); }

// block of 256 threads (8 warps). red: >= 8*N floats smem, out: >= N floats smem
template<int N>
__device__ __forceinline__ void block_reduce(float* v, float* red, float* out){
    int lane = threadIdx.x & 31, w = threadIdx.x >> 5;
    #pragma unroll
    for (int i = 0; i < N; i++){
        float x = v[i];
        #pragma unroll
        for (int o = 16; o; o >>= 1) x += __shfl_xor_sync(0xffffffffu, x, o);
        if (lane == 0) red[w*N + i] = x;
    }
    __syncthreads();
    if (threadIdx.x < N){
        float s = 0.f;
        #pragma unroll
        for (int ww = 0; ww < 8; ww++) s += red[ww*N + threadIdx.x];
        out[threadIdx.x] = s;
    }
    __syncthreads();
}

// ---------------- kernel A: prompts P/S + history, build packed consts ----------------
__global__ __launch_bounds__(256)
void k_prompt(const int* uid, const float* Pm, const float* Sm,
              const float* Wk, const float* bk, const float* Wv, const float* bv,
              const float* zg, const float* zb, const float* sg, const float* sb,
              const float* ng, const float* nb,
              const float* pzbuf, const float* psbuf, int LP)
{
    extern __shared__ float sm[];
    float* Wks  = sm;              // 4096
    float* Wvs  = sm + 4096;       // 4096
    float* bufA = sm + 8192;       // 4096  (Ps_ln)
    float* bufB = sm + 12288;      // 4096  (Ss_ln -> pnam scratch)
    float* xr   = sm + 16384;      // 64
    float* zr   = xr + 64;         // 64
    float* vr   = zr + 64;         // 64
    float* zl   = vr + 64;         // 64 (S_z_ln)
    float* red  = zl + 64;         // 64
    float* outr = red + 64;        // 8

    int tid = threadIdx.x, b = blockIdx.x;
    int p = tid & 63, d0 = (tid >> 6) * 16;

    if (b == 0 && tid == 0){ g_acc[0] = 0.0; g_acc[1] = 0.0; }

    for (int i = tid; i < 4096; i += 256){ Wks[i] = Wk[i]; Wvs[i] = Wv[i]; }
    __syncthreads();

    for (int pass = 0; pass < 2; pass++){
        const float* X = pass ? Sm : Pm;
        float acc[16];
        #pragma unroll
        for (int i = 0; i < 16; i++) acc[i] = 0.f;
        float zs = 0.f;

        for (int r = 0; r < LP; r++){
            if (tid < 64) xr[tid] = X[(b*LP + r)*64 + tid];
            __syncthreads();
            if (tid < 64){
                float s = bk[tid];
                #pragma unroll
                for (int k = 0; k < 64; k++) s += xr[k] * Wks[k*64 + tid];
                zr[tid] = eluf(s);
            } else if (tid < 128){
                int t = tid - 64; float s = bv[t];
                #pragma unroll
                for (int k = 0; k < 64; k++) s += xr[k] * Wvs[k*64 + t];
                vr[t] = s;
            }
            __syncthreads();
            float vv = vr[p];
            #pragma unroll
            for (int i = 0; i < 16; i++) acc[i] += zr[d0 + i] * vv;
            if (tid < 64) zs += zr[tid];
            __syncthreads();
        }
        // LN over z (D=64); EPS shift cancels in mean-subtraction
        float rv[2]; rv[0] = (tid < 64) ? zs : 0.f; rv[1] = (tid < 64) ? zs*zs : 0.f;
        block_reduce<2>(rv, red, outr);
        float mz = outr[0] * (1.f/64.f);
        float ivz = rsqrtf(outr[1]*(1.f/64.f) - mz*mz + LN_EPS);
        if (tid < 64){
            float zln = (zs - mz) * ivz * zg[tid] + zb[tid];
            if (pass == 0) g_Pz[b*64 + tid] = zln; else zl[tid] = zln;
        }
        // LN over s (D*D=4096)
        float sv[2] = {0.f, 0.f};
        #pragma unroll
        for (int i = 0; i < 16; i++){ sv[0] += acc[i]; sv[1] += acc[i]*acc[i]; }
        block_reduce<2>(sv, red, outr);
        float ms = outr[0] * (1.f/4096.f);
        float ivs = rsqrtf(outr[1]*(1.f/4096.f) - ms*ms + LN_EPS);
        float* buf = pass ? bufB : bufA;
        #pragma unroll
        for (int i = 0; i < 16; i++){
            int e = (d0 + i)*64 + p;
            buf[e] = (acc[i] - ms) * ivs * sg[e] + sb[e];
        }
        __syncthreads();
    }

    // history path
    int u = uid[b];
    float pzv = 0.f;
    if (tid < 64) pzv = pzbuf[(size_t)u*64 + tid] + zl[tid];
    float rv1[1]; rv1[0] = (tid < 64) ? pzv*pzv : 0.f;
    block_reduce<1>(rv1, red, outr);
    float ipn = 1.f / (fmaxf(sqrtf(outr[0]), 1e-8f) + EPS);

    float pn16[16]; float sv[2] = {0.f, 0.f};
    #pragma unroll
    for (int k2 = 0; k2 < 16; k2++){
        int e = tid + k2*256;
        float pv = (psbuf[(size_t)u*4096 + e] + bufB[e]) * ipn;
        pn16[k2] = pv; sv[0] += pv; sv[1] += pv*pv;
    }
    block_reduce<2>(sv, red, outr);
    float mp = outr[0] * (1.f/4096.f);
    float ivp = rsqrtf(outr[1]*(1.f/4096.f) - mp*mp + LN_EPS);
    #pragma unroll
    for (int k2 = 0; k2 < 16; k2++){
        int e = tid + k2*256;
        float M = (pn16[k2] - mp) * ivp * ng[e] + nb[e];
        g_pack[b*4096 + e] = make_float4(sg[e], sb[e] + bufA[e], ng[e], nb[e] + M);
    }
}

// ---------------- kernel B: q/z/v GEMVs + per-chunk partial sums ----------------
__global__ __launch_bounds__(256)
void k_phase1(const float* X, const float* Wq, const float* bq,
              const float* Wk, const float* bk, const float* Wv, const float* bv,
              int NCH)
{
    extern __shared__ float sm[];
    float* Wqs = sm;             // 4096
    float* Wks = sm + 4096;      // 4096
    float* Wvs = sm + 8192;      // 4096
    float* xr  = sm + 12288;     // 64
    float* zr  = xr + 64;        // 64
    float* vr  = zr + 64;        // 64
    float* qn  = vr + 64;        // 8

    int tid = threadIdx.x;
    int b = blockIdx.x / NCH, ch = blockIdx.x % NCH;
    int p = tid & 63, d0 = (tid >> 6) * 16;
    int L = NCH * CHUNK;

    for (int i = tid; i < 4096; i += 256){ Wqs[i] = Wq[i]; Wks[i] = Wk[i]; Wvs[i] = Wv[i]; }
    __syncthreads();

    float acc[16];
    #pragma unroll
    for (int i = 0; i < 16; i++) acc[i] = 0.f;
    float zs = 0.f;

    for (int r = 0; r < CHUNK; r++){
        int l = ch*CHUNK + r;
        size_t idx = ((size_t)b*L + l) * 64;
        if (tid < 64) xr[tid] = X[idx + tid];
        __syncthreads();
        if (tid < 64){
            float s = bq[tid];
            #pragma unroll
            for (int k = 0; k < 64; k++) s += xr[k] * Wqs[k*64 + tid];
            float qv = eluf(s);
            g_q[idx + tid] = qv;
            float qq = qv*qv;
            #pragma unroll
            for (int o = 16; o; o >>= 1) qq += __shfl_xor_sync(0xffffffffu, qq, o);
            if ((tid & 31) == 0) qn[tid >> 5] = qq;
        } else if (tid < 128){
            int t = tid - 64; float s = bk[t];
            #pragma unroll
            for (int k = 0; k < 64; k++) s += xr[k] * Wks[k*64 + t];
            float zv = eluf(s);
            zr[t] = zv; g_z[idx + t] = zv;
        } else if (tid < 192){
            int t = tid - 128; float s = bv[t];
            #pragma unroll
            for (int k = 0; k < 64; k++) s += xr[k] * Wvs[k*64 + t];
            vr[t] = s; g_v[idx + t] = s;
        }
        __syncthreads();
        if (tid == 0) g_rqn[(size_t)b*L + l] = 1.f / fmaxf(sqrtf(qn[0] + qn[1]), 1e-8f);
        float vv = vr[p];
        #pragma unroll
        for (int i = 0; i < 16; i++) acc[i] += zr[d0 + i] * vv;
        if (tid < 64) zs += zr[tid];
        __syncthreads();
    }
    size_t o = (size_t)(b*NCH + ch) * 4160;
    #pragma unroll
    for (int i = 0; i < 16; i++) g_part[o + (d0 + i)*64 + p] = acc[i];
    if (tid < 64) g_part[o + 4096 + tid] = zs;
}

// ---------------- kernel C: exclusive prefix of chunk partials per batch ----------------
__global__ __launch_bounds__(256)
void k_prefix(int NCH)
{
    int b = blockIdx.x, tid = threadIdx.x;
    float run[17];
    #pragma unroll
    for (int k = 0; k < 17; k++) run[k] = 0.f;
    for (int ch = 0; ch < NCH; ch++){
        size_t o = (size_t)(b*NCH + ch) * 4160;
        #pragma unroll
        for (int k = 0; k < 17; k++){
            int e = tid + k*256;
            if (e < 4160){ g_base[o + e] = run[k]; run[k] += g_part[o + e]; }
        }
    }
}

// ---------------- kernel D: main per-step scan ----------------
__global__ __launch_bounds__(256)
void k_main(const float* zg, const float* zb, const float* nag, const float* nab,
            float* out, int NCH)
{
    extern __shared__ float sm[];
    float4* pk   = (float4*)sm;          // 4096 float4 (16384 floats)
    float* zst   = sm + 16384;           // 64
    float* vst   = zst + 64;             // 64
    float* qst   = vst + 64;             // 64
    float* zpx   = qst + 64;             // 64  z_g
    float* zpy   = zpx + 64;             // 64  z_b + Pz
    float* nagz  = zpy + 64;             // 64
    float* nabz  = nagz + 64;            // 64
    float* na_part = nabz + 64;          // 256
    float* red   = na_part + 256;        // 64
    float* outr  = red + 64;             // 8
    float* srq   = outr + 8;             // 4

    int tid = threadIdx.x;
    int b = blockIdx.x / NCH, ch = blockIdx.x % NCH;
    int p = tid & 63, d0 = (tid >> 6) * 16;
    int L = NCH * CHUNK;

    for (int i = tid; i < 4096; i += 256) pk[i] = g_pack[b*4096 + i];
    if (tid < 64){
        zpx[tid] = zg[tid];
        zpy[tid] = zb[tid] + g_Pz[b*64 + tid];
        nagz[tid] = nag[tid];
        nabz[tid] = nab[tid];
    }
    float A[16];
    size_t ob = (size_t)(b*NCH + ch) * 4160;
    #pragma unroll
    for (int i = 0; i < 16; i++) A[i] = g_base[ob + (d0 + i)*64 + p];
    float zc = (tid < 64) ? g_base[ob + 4096 + tid] : 0.f;
    double dsum = 0.0, dsq = 0.0;
    __syncthreads();

    for (int r = 0; r < CHUNK; r++){
        int l = ch*CHUNK + r;
        size_t idx = ((size_t)b*L + l) * 64;
        if (tid < 64)        zst[tid]      = g_z[idx + tid];
        else if (tid < 128)  vst[tid - 64] = g_v[idx + tid - 64];
        else if (tid < 192)  qst[tid - 128]= g_q[idx + tid - 128];
        else if (tid == 192) srq[0]        = g_rqn[(size_t)b*L + l];
        __syncthreads();

        if (tid < 64) zc += zst[tid];
        float vv = vst[p];
        float rv[4] = {0.f, 0.f, 0.f, 0.f};
        #pragma unroll
        for (int i = 0; i < 16; i++){
            A[i] += zst[d0 + i] * vv;
            rv[0] += A[i]; rv[1] += A[i]*A[i];
        }
        if (tid < 64){ rv[2] = zc; rv[3] = zc*zc; }
        block_reduce<4>(rv, red, outr);
        float aBar = outr[0] * (1.f/4096.f);
        float ivs  = rsqrtf(outr[1]*(1.f/4096.f) - aBar*aBar + LN_EPS);
        float mzv  = outr[2] * (1.f/64.f);
        float ivz  = rsqrtf(outr[3]*(1.f/64.f) - mzv*mzv + LN_EPS);

        float sv[3] = {0.f, 0.f, 0.f};
        float st[16];
        #pragma unroll
        for (int i = 0; i < 16; i++){
            float4 w = pk[(d0 + i)*64 + p];
            float t = (A[i] - aBar) * ivs;
            st[i] = t * w.x + w.y;               // s_ln + Ps
            sv[0] += st[i]; sv[1] += st[i]*st[i];
        }
        if (tid < 64){
            float zt = (zc - mzv) * ivz * zpx[tid] + zpy[tid];   // z_tot
            sv[2] = zt*zt;
            float rr = qst[tid] / fmaxf(zt, 1e-6f);
            dsum += (double)rr; dsq += (double)rr * (double)rr;
        }
        block_reduce<3>(sv, red, outr);
        float zn   = fmaxf(sqrtf(outr[2]), 1e-8f);
        float izn  = 1.f / zn;
        float mst  = outr[0] * (1.f/4096.f);
        float mnam = mst * izn;
        float vnam = (outr[1]*(1.f/4096.f) - mst*mst) * izn * izn;
        float ivn  = rsqrtf(vnam + LN_EPS);
        float k1   = izn * ivn, k0 = -mnam * ivn;

        float accn = 0.f;
        #pragma unroll
        for (int i = 0; i < 16; i++){
            float4 w = pk[(d0 + i)*64 + p];
            float a = st[i] * k1 + k0;
            accn += qst[d0 + i] * (a * w.z + w.w);   // includes +Mprev via w.w
        }
        na_part[tid] = accn;
        __syncthreads();

        float nv = 0.f;
        if (tid < 64){
            nv = (na_part[tid] + na_part[tid+64] + na_part[tid+128] + na_part[tid+192]) * srq[0];
            float s1 = nv, s2 = nv*nv;
            #pragma unroll
            for (int o = 16; o; o >>= 1){
                s1 += __shfl_xor_sync(0xffffffffu, s1, o);
                s2 += __shfl_xor_sync(0xffffffffu, s2, o);
            }
            if ((tid & 31) == 0){ red[(tid>>5)*2] = s1; red[(tid>>5)*2 + 1] = s2; }
        }
        __syncthreads();
        if (tid < 64){
            float S1 = red[0] + red[2], S2 = red[1] + red[3];
            float mn = S1 * (1.f/64.f);
            float iv = rsqrtf(S2*(1.f/64.f) - mn*mn + LN_EPS);
            out[idx + tid] = (nv - mn) * iv * nagz[tid] + nabz[tid];
        }
        __syncthreads();   // protect red/zst/etc. before next iteration
    }

    // reduce local double sums -> global
    __syncthreads();
    double* db = (double*)sm;
    if (tid < 64){ db[tid] = dsum; db[64 + tid] = dsq; }
    __syncthreads();
    if (tid == 0){
        double a = 0.0, c = 0.0;
        for (int i = 0; i < 64; i++){ a += db[i]; c += db[64 + i]; }
        atomicAdd(&g_acc[0], a);
        atomicAdd(&g_acc[1], c);
    }
}

// ---------------- kernel E: finalize std ----------------
__global__ void k_std(float* out, int n, int outpos)
{
    double mean = g_acc[0] / (double)n;
    double var  = (g_acc[1] - g_acc[0]*mean) / (double)(n - 1);
    out[outpos] = (float)sqrt(var);
}

// ---------------- launch ----------------
extern "C" void kernel_launch(void* const* d_in, const int* in_sizes, int n_in,
                              void* d_out, int out_size)
{
    const int*   uid   = (const int*)  d_in[0];
    const float* X     = (const float*)d_in[1];
    const float* Pm    = (const float*)d_in[2];
    const float* Sm    = (const float*)d_in[3];
    const float* Wq    = (const float*)d_in[4];
    const float* bq    = (const float*)d_in[5];
    const float* Wk    = (const float*)d_in[6];
    const float* bk    = (const float*)d_in[7];
    const float* Wv    = (const float*)d_in[8];
    const float* bv    = (const float*)d_in[9];
    const float* zg    = (const float*)d_in[10];
    const float* zb    = (const float*)d_in[11];
    const float* sg    = (const float*)d_in[12];
    const float* sb    = (const float*)d_in[13];
    const float* ng    = (const float*)d_in[14];
    const float* nb    = (const float*)d_in[15];
    const float* nag   = (const float*)d_in[16];
    const float* nab   = (const float*)d_in[17];
    const float* pzbuf = (const float*)d_in[18];
    const float* psbuf = (const float*)d_in[19];
    float* out = (float*)d_out;

    int B   = in_sizes[0];
    int L   = in_sizes[1] / (B * 64);
    int LP  = in_sizes[2] / (B * 64);
    int NCH = L / CHUNK;

    size_t smA = (size_t)(16384 + 64*4 + 64 + 8) * 4;           // ~66.8 KB
    size_t smB = (size_t)(12288 + 64*3 + 8) * 4;                // ~49.9 KB
    size_t smD = (size_t)(16384 + 64*3 + 64*4 + 256 + 64 + 8 + 4) * 4; // ~68.7 KB

    cudaFuncSetAttribute(k_prompt, cudaFuncAttributeMaxDynamicSharedMemorySize, (int)smA);
    cudaFuncSetAttribute(k_phase1, cudaFuncAttributeMaxDynamicSharedMemorySize, (int)smB);
    cudaFuncSetAttribute(k_main,   cudaFuncAttributeMaxDynamicSharedMemorySize, (int)smD);

    k_prompt<<<B, 256, smA>>>(uid, Pm, Sm, Wk, bk, Wv, bv, zg, zb, sg, sb, ng, nb,
                              pzbuf, psbuf, LP);
    k_phase1<<<B*NCH, 256, smB>>>(X, Wq, bq, Wk, bk, Wv, bv, NCH);
    k_prefix<<<B, 256>>>(NCH);
    k_main<<<B*NCH, 256, smD>>>(zg, zb, nag, nab, out, NCH);
    k_std<<<1, 1>>>(out, B*L*64, out_size - 1);
}

// round 6
// speedup vs baseline: 1.0040x; 1.0040x over previous
#include <cuda_runtime.h>
#include <math.h>

#define EPS 1e-8f
#define LN_EPS 1e-5f
#define CHUNK 32

// ---------------- scratch (static __device__, no allocs) ----------------
__device__ float  g_q[16*512*64];
__device__ float  g_z[16*512*64];
__device__ float  g_v[16*512*64];
__device__ float  g_rqn[16*512];
__device__ float  g_part[16*16*4160];
__device__ float  g_base[16*16*4160];
__device__ float4 g_pack[16*4096];      // {sg, sb+Ps_ln, ng, nb+Mprev_ln}
__device__ float  g_Pz[16*64];          // P_z_ln last step per batch
__device__ double g_acc[2];             // sum, sumsq for std

__device__ __forceinline__ float eluf(float x){ return x > 0.f ? x : (expf(x) - 1.f); }

// block of 256 threads (8 warps). red: >= 8*N floats smem, out: >= N floats smem
template<int N>
__device__ __forceinline__ void block_reduce(float* v, float* red, float* out){
    int lane = threadIdx.x & 31, w = threadIdx.x >> 5;
    #pragma unroll
    for (int i = 0; i < N; i++){
        float x = v[i];
        #pragma unroll
        for (int o = 16; o; o >>= 1) x += __shfl_xor_sync(0xffffffffu, x, o);
        if (lane == 0) red[w*N + i] = x;
    }
    __syncthreads();
    if (threadIdx.x < N){
        float s = 0.f;
        #pragma unroll
        for (int ww = 0; ww < 8; ww++) s += red[ww*N + threadIdx.x];
        out[threadIdx.x] = s;
    }
    __syncthreads();
}

// ---------------- kernel A: prompts P/S + history, build packed consts ----------------
__global__ __launch_bounds__(256)
void k_prompt(const int* uid, const float* Pm, const float* Sm,
              const float* Wk, const float* bk, const float* Wv, const float* bv,
              const float* zg, const float* zb, const float* sg, const float* sb,
              const float* ng, const float* nb,
              const float* pzbuf, const float* psbuf, int LP)
{
    extern __shared__ float sm[];
    float* Wks  = sm;              // 4096
    float* Wvs  = sm + 4096;       // 4096
    float* bufA = sm + 8192;       // 4096  (Ps_ln)
    float* bufB = sm + 12288;      // 4096  (Ss_ln -> pnam scratch)
    float* xr   = sm + 16384;      // 64
    float* zr   = xr + 64;         // 64
    float* vr   = zr + 64;         // 64
    float* zl   = vr + 64;         // 64 (S_z_ln)
    float* red  = zl + 64;         // 64
    float* outr = red + 64;        // 8

    int tid = threadIdx.x, b = blockIdx.x;
    int p = tid & 63, d0 = (tid >> 6) * 16;

    if (b == 0 && tid == 0){ g_acc[0] = 0.0; g_acc[1] = 0.0; }

    for (int i = tid; i < 4096; i += 256){ Wks[i] = Wk[i]; Wvs[i] = Wv[i]; }
    __syncthreads();

    for (int pass = 0; pass < 2; pass++){
        const float* X = pass ? Sm : Pm;
        float acc[16];
        #pragma unroll
        for (int i = 0; i < 16; i++) acc[i] = 0.f;
        float zs = 0.f;

        for (int r = 0; r < LP; r++){
            if (tid < 64) xr[tid] = X[(b*LP + r)*64 + tid];
            __syncthreads();
            if (tid < 64){
                float s = bk[tid];
                #pragma unroll
                for (int k = 0; k < 64; k++) s += xr[k] * Wks[k*64 + tid];
                zr[tid] = eluf(s);
            } else if (tid < 128){
                int t = tid - 64; float s = bv[t];
                #pragma unroll
                for (int k = 0; k < 64; k++) s += xr[k] * Wvs[k*64 + t];
                vr[t] = s;
            }
            __syncthreads();
            float vv = vr[p];
            #pragma unroll
            for (int i = 0; i < 16; i++) acc[i] += zr[d0 + i] * vv;
            if (tid < 64) zs += zr[tid];
            __syncthreads();
        }
        // LN over z (D=64); EPS shift cancels in mean-subtraction
        float rv[2]; rv[0] = (tid < 64) ? zs : 0.f; rv[1] = (tid < 64) ? zs*zs : 0.f;
        block_reduce<2>(rv, red, outr);
        float mz = outr[0] * (1.f/64.f);
        float ivz = rsqrtf(outr[1]*(1.f/64.f) - mz*mz + LN_EPS);
        if (tid < 64){
            float zln = (zs - mz) * ivz * zg[tid] + zb[tid];
            if (pass == 0) g_Pz[b*64 + tid] = zln; else zl[tid] = zln;
        }
        // LN over s (D*D=4096)
        float sv[2] = {0.f, 0.f};
        #pragma unroll
        for (int i = 0; i < 16; i++){ sv[0] += acc[i]; sv[1] += acc[i]*acc[i]; }
        block_reduce<2>(sv, red, outr);
        float ms = outr[0] * (1.f/4096.f);
        float ivs = rsqrtf(outr[1]*(1.f/4096.f) - ms*ms + LN_EPS);
        float* buf = pass ? bufB : bufA;
        #pragma unroll
        for (int i = 0; i < 16; i++){
            int e = (d0 + i)*64 + p;
            buf[e] = (acc[i] - ms) * ivs * sg[e] + sb[e];
        }
        __syncthreads();
    }

    // history path
    int u = uid[b];
    float pzv = 0.f;
    if (tid < 64) pzv = pzbuf[(size_t)u*64 + tid] + zl[tid];
    float rv1[1]; rv1[0] = (tid < 64) ? pzv*pzv : 0.f;
    block_reduce<1>(rv1, red, outr);
    float ipn = 1.f / (fmaxf(sqrtf(outr[0]), 1e-8f) + EPS);

    float pn16[16]; float sv[2] = {0.f, 0.f};
    #pragma unroll
    for (int k2 = 0; k2 < 16; k2++){
        int e = tid + k2*256;
        float pv = (psbuf[(size_t)u*4096 + e] + bufB[e]) * ipn;
        pn16[k2] = pv; sv[0] += pv; sv[1] += pv*pv;
    }
    block_reduce<2>(sv, red, outr);
    float mp = outr[0] * (1.f/4096.f);
    float ivp = rsqrtf(outr[1]*(1.f/4096.f) - mp*mp + LN_EPS);
    #pragma unroll
    for (int k2 = 0; k2 < 16; k2++){
        int e = tid + k2*256;
        float M = (pn16[k2] - mp) * ivp * ng[e] + nb[e];
        g_pack[b*4096 + e] = make_float4(sg[e], sb[e] + bufA[e], ng[e], nb[e] + M);
    }
}

// ---------------- kernel B: q/z/v GEMVs + per-chunk partial sums ----------------
__global__ __launch_bounds__(256)
void k_phase1(const float* X, const float* Wq, const float* bq,
              const float* Wk, const float* bk, const float* Wv, const float* bv,
              int NCH)
{
    extern __shared__ float sm[];
    float* Wqs = sm;             // 4096
    float* Wks = sm + 4096;      // 4096
    float* Wvs = sm + 8192;      // 4096
    float* xr  = sm + 12288;     // 64
    float* zr  = xr + 64;        // 64
    float* vr  = zr + 64;        // 64
    float* qn  = vr + 64;        // 8

    int tid = threadIdx.x;
    int b = blockIdx.x / NCH, ch = blockIdx.x % NCH;
    int p = tid & 63, d0 = (tid >> 6) * 16;
    int L = NCH * CHUNK;

    for (int i = tid; i < 4096; i += 256){ Wqs[i] = Wq[i]; Wks[i] = Wk[i]; Wvs[i] = Wv[i]; }
    __syncthreads();

    float acc[16];
    #pragma unroll
    for (int i = 0; i < 16; i++) acc[i] = 0.f;
    float zs = 0.f;

    for (int r = 0; r < CHUNK; r++){
        int l = ch*CHUNK + r;
        size_t idx = ((size_t)b*L + l) * 64;
        if (tid < 64) xr[tid] = X[idx + tid];
        __syncthreads();
        if (tid < 64){
            float s = bq[tid];
            #pragma unroll
            for (int k = 0; k < 64; k++) s += xr[k] * Wqs[k*64 + tid];
            float qv = eluf(s);
            g_q[idx + tid] = qv;
            float qq = qv*qv;
            #pragma unroll
            for (int o = 16; o; o >>= 1) qq += __shfl_xor_sync(0xffffffffu, qq, o);
            if ((tid & 31) == 0) qn[tid >> 5] = qq;
        } else if (tid < 128){
            int t = tid - 64; float s = bk[t];
            #pragma unroll
            for (int k = 0; k < 64; k++) s += xr[k] * Wks[k*64 + t];
            float zv = eluf(s);
            zr[t] = zv; g_z[idx + t] = zv;
        } else if (tid < 192){
            int t = tid - 128; float s = bv[t];
            #pragma unroll
            for (int k = 0; k < 64; k++) s += xr[k] * Wvs[k*64 + t];
            vr[t] = s; g_v[idx + t] = s;
        }
        __syncthreads();
        if (tid == 0) g_rqn[(size_t)b*L + l] = 1.f / fmaxf(sqrtf(qn[0] + qn[1]), 1e-8f);
        float vv = vr[p];
        #pragma unroll
        for (int i = 0; i < 16; i++) acc[i] += zr[d0 + i] * vv;
        if (tid < 64) zs += zr[tid];
        __syncthreads();
    }
    size_t o = (size_t)(b*NCH + ch) * 4160;
    #pragma unroll
    for (int i = 0; i < 16; i++) g_part[o + (d0 + i)*64 + p] = acc[i];
    if (tid < 64) g_part[o + 4096 + tid] = zs;
}

// ---------------- kernel C: exclusive prefix of chunk partials per batch ----------------
__global__ __launch_bounds__(256)
void k_prefix(int NCH)
{
    int b = blockIdx.x, tid = threadIdx.x;
    float run[17];
    #pragma unroll
    for (int k = 0; k < 17; k++) run[k] = 0.f;
    for (int ch = 0; ch < NCH; ch++){
        size_t o = (size_t)(b*NCH + ch) * 4160;
        #pragma unroll
        for (int k = 0; k < 17; k++){
            int e = tid + k*256;
            if (e < 4160){ g_base[o + e] = run[k]; run[k] += g_part[o + e]; }
        }
    }
}

// ---------------- kernel D: main per-step scan ----------------
__global__ __launch_bounds__(256)
void k_main(const float* zg, const float* zb, const float* nag, const float* nab,
            float* out, int NCH)
{
    extern __shared__ float sm[];
    float4* pk   = (float4*)sm;          // 4096 float4 (16384 floats)
    float* zst   = sm + 16384;           // 64
    float* vst   = zst + 64;             // 64
    float* qst   = vst + 64;             // 64
    float* zpx   = qst + 64;             // 64  z_g
    float* zpy   = zpx + 64;             // 64  z_b + Pz
    float* nagz  = zpy + 64;             // 64
    float* nabz  = nagz + 64;            // 64
    float* na_part = nabz + 64;          // 256
    float* red   = na_part + 256;        // 64
    float* outr  = red + 64;             // 8
    float* srq   = outr + 8;             // 4

    int tid = threadIdx.x;
    int b = blockIdx.x / NCH, ch = blockIdx.x % NCH;
    int p = tid & 63, d0 = (tid >> 6) * 16;
    int L = NCH * CHUNK;

    for (int i = tid; i < 4096; i += 256) pk[i] = g_pack[b*4096 + i];
    if (tid < 64){
        zpx[tid] = zg[tid];
        zpy[tid] = zb[tid] + g_Pz[b*64 + tid];
        nagz[tid] = nag[tid];
        nabz[tid] = nab[tid];
    }
    float A[16];
    size_t ob = (size_t)(b*NCH + ch) * 4160;
    #pragma unroll
    for (int i = 0; i < 16; i++) A[i] = g_base[ob + (d0 + i)*64 + p];
    float zc = (tid < 64) ? g_base[ob + 4096 + tid] : 0.f;
    double dsum = 0.0, dsq = 0.0;
    __syncthreads();

    for (int r = 0; r < CHUNK; r++){
        int l = ch*CHUNK + r;
        size_t idx = ((size_t)b*L + l) * 64;
        if (tid < 64)        zst[tid]      = g_z[idx + tid];
        else if (tid < 128)  vst[tid - 64] = g_v[idx + tid - 64];
        else if (tid < 192)  qst[tid - 128]= g_q[idx + tid - 128];
        else if (tid == 192) srq[0]        = g_rqn[(size_t)b*L + l];
        __syncthreads();

        if (tid < 64) zc += zst[tid];
        float vv = vst[p];
        float rv[4] = {0.f, 0.f, 0.f, 0.f};
        #pragma unroll
        for (int i = 0; i < 16; i++){
            A[i] += zst[d0 + i] * vv;
            rv[0] += A[i]; rv[1] += A[i]*A[i];
        }
        if (tid < 64){ rv[2] = zc; rv[3] = zc*zc; }
        block_reduce<4>(rv, red, outr);
        float aBar = outr[0] * (1.f/4096.f);
        float ivs  = rsqrtf(outr[1]*(1.f/4096.f) - aBar*aBar + LN_EPS);
        float mzv  = outr[2] * (1.f/64.f);
        float ivz  = rsqrtf(outr[3]*(1.f/64.f) - mzv*mzv + LN_EPS);

        float sv[3] = {0.f, 0.f, 0.f};
        float st[16];
        #pragma unroll
        for (int i = 0; i < 16; i++){
            float4 w = pk[(d0 + i)*64 + p];
            float t = (A[i] - aBar) * ivs;
            st[i] = t * w.x + w.y;               // s_ln + Ps
            sv[0] += st[i]; sv[1] += st[i]*st[i];
        }
        if (tid < 64){
            float zt = (zc - mzv) * ivz * zpx[tid] + zpy[tid];   // z_tot
            sv[2] = zt*zt;
            float rr = qst[tid] / fmaxf(zt, 1e-6f);
            dsum += (double)rr; dsq += (double)rr * (double)rr;
        }
        block_reduce<3>(sv, red, outr);
        float zn   = fmaxf(sqrtf(outr[2]), 1e-8f);
        float izn  = 1.f / zn;
        float mst  = outr[0] * (1.f/4096.f);
        float mnam = mst * izn;
        float vnam = (outr[1]*(1.f/4096.f) - mst*mst) * izn * izn;
        float ivn  = rsqrtf(vnam + LN_EPS);
        float k1   = izn * ivn, k0 = -mnam * ivn;

        float accn = 0.f;
        #pragma unroll
        for (int i = 0; i < 16; i++){
            float4 w = pk[(d0 + i)*64 + p];
            float a = st[i] * k1 + k0;
            accn += qst[d0 + i] * (a * w.z + w.w);   // includes +Mprev via w.w
        }
        na_part[tid] = accn;
        __syncthreads();

        float nv = 0.f;
        if (tid < 64){
            nv = (na_part[tid] + na_part[tid+64] + na_part[tid+128] + na_part[tid+192]) * srq[0];
            float s1 = nv, s2 = nv*nv;
            #pragma unroll
            for (int o = 16; o; o >>= 1){
                s1 += __shfl_xor_sync(0xffffffffu, s1, o);
                s2 += __shfl_xor_sync(0xffffffffu, s2, o);
            }
            if ((tid & 31) == 0){ red[(tid>>5)*2] = s1; red[(tid>>5)*2 + 1] = s2; }
        }
        __syncthreads();
        if (tid < 64){
            float S1 = red[0] + red[2], S2 = red[1] + red[3];
            float mn = S1 * (1.f/64.f);
            float iv = rsqrtf(S2*(1.f/64.f) - mn*mn + LN_EPS);
            out[idx + tid] = (nv - mn) * iv * nagz[tid] + nabz[tid];
        }
        __syncthreads();   // protect red/zst/etc. before next iteration
    }

    // reduce local double sums -> global
    __syncthreads();
    double* db = (double*)sm;
    if (tid < 64){ db[tid] = dsum; db[64 + tid] = dsq; }
    __syncthreads();
    if (tid == 0){
        double a = 0.0, c = 0.0;
        for (int i = 0; i < 64; i++){ a += db[i]; c += db[64 + i]; }
        atomicAdd(&g_acc[0], a);
        atomicAdd(&g_acc[1], c);
    }
}

// ---------------- kernel E: finalize std ----------------
__global__ void k_std(float* out, int n, int outpos)
{
    double mean = g_acc[0] / (double)n;
    double var  = (g_acc[1] - g_acc[0]*mean) / (double)(n - 1);
    out[outpos] = (float)sqrt(var);
}

// ---------------- launch ----------------
extern "C" void kernel_launch(void* const* d_in, const int* in_sizes, int n_in,
                              void* d_out, int out_size)
{
    const int*   uid   = (const int*)  d_in[0];
    const float* X     = (const float*)d_in[1];
    const float* Pm    = (const float*)d_in[2];
    const float* Sm    = (const float*)d_in[3];
    const float* Wq    = (const float*)d_in[4];
    const float* bq    = (const float*)d_in[5];
    const float* Wk    = (const float*)d_in[6];
    const float* bk    = (const float*)d_in[7];
    const float* Wv    = (const float*)d_in[8];
    const float* bv    = (const float*)d_in[9];
    const float* zg    = (const float*)d_in[10];
    const float* zb    = (const float*)d_in[11];
    const float* sg    = (const float*)d_in[12];
    const float* sb    = (const float*)d_in[13];
    const float* ng    = (const float*)d_in[14];
    const float* nb    = (const float*)d_in[15];
    const float* nag   = (const float*)d_in[16];
    const float* nab   = (const float*)d_in[17];
    const float* pzbuf = (const float*)d_in[18];
    const float* psbuf = (const float*)d_in[19];
    float* out = (float*)d_out;

    int B   = in_sizes[0];
    int L   = in_sizes[1] / (B * 64);
    int LP  = in_sizes[2] / (B * 64);
    int NCH = L / CHUNK;

    size_t smA = (size_t)(16384 + 64*4 + 64 + 8) * 4;           // ~66.8 KB
    size_t smB = (size_t)(12288 + 64*3 + 8) * 4;                // ~49.9 KB
    size_t smD = (size_t)(16384 + 64*3 + 64*4 + 256 + 64 + 8 + 4) * 4; // ~68.7 KB

    cudaFuncSetAttribute(k_prompt, cudaFuncAttributeMaxDynamicSharedMemorySize, (int)smA);
    cudaFuncSetAttribute(k_phase1, cudaFuncAttributeMaxDynamicSharedMemorySize, (int)smB);
    cudaFuncSetAttribute(k_main,   cudaFuncAttributeMaxDynamicSharedMemorySize, (int)smD);

    k_prompt<<<B, 256, smA>>>(uid, Pm, Sm, Wk, bk, Wv, bv, zg, zb, sg, sb, ng, nb,
                              pzbuf, psbuf, LP);
    k_phase1<<<B*NCH, 256, smB>>>(X, Wq, bq, Wk, bk, Wv, bv, NCH);
    k_prefix<<<B, 256>>>(NCH);
    k_main<<<B*NCH, 256, smD>>>(zg, zb, nag, nab, out, NCH);
    k_std<<<1, 1>>>(out, B*L*64, out_size - 1);
}

// round 7
// speedup vs baseline: 1.4408x; 1.4350x over previous
#include <cuda_runtime.h>
#include <math.h>

#define EPS 1e-8f
#define LN_EPS 1e-5f
#define CHUNK 32

// ---------------- scratch (static __device__, no allocs) ----------------
__device__ float  g_q[16*512*64];
__device__ float  g_z[16*512*64];
__device__ float  g_v[16*512*64];
__device__ float  g_part[16*16*4160];
__device__ float  g_base[16*16*4160];
__device__ float4 g_pack[16*4096];      // {sg, sb+Ps_ln, ng, nb+Mprev_ln}
__device__ float  g_Pz[16*64];          // P_z_ln last step per batch
__device__ double g_acc[2];             // sum, sumsq for std

__device__ __forceinline__ float eluf(float x){ return x > 0.f ? x : (expf(x) - 1.f); }

// one-sync block reduce for 256 threads (8 warps). Results broadcast to ALL
// threads in out[] (registers). red must be a buffer of >= 8*N floats that is
// not re-written until at least one block-wide sync after this call returns
// (use alternating buffers for back-to-back calls).
template<int N>
__device__ __forceinline__ void block_reduce_b(const float* v, float* red, float* out){
    int lane = threadIdx.x & 31, w = threadIdx.x >> 5;
    #pragma unroll
    for (int i = 0; i < N; i++){
        float x = v[i];
        #pragma unroll
        for (int o = 16; o; o >>= 1) x += __shfl_xor_sync(0xffffffffu, x, o);
        if (lane == 0) red[w*N + i] = x;
    }
    __syncthreads();
    #pragma unroll
    for (int i = 0; i < N; i++){
        float s = 0.f;
        #pragma unroll
        for (int ww2 = 0; ww2 < 8; ww2++) s += red[ww2*N + i];
        out[i] = s;
    }
}

// ---------------- kernel A: prompts P/S + history, build packed consts ----------------
__global__ __launch_bounds__(256)
void k_prompt(const int* uid, const float* Pm, const float* Sm,
              const float* Wk, const float* bk, const float* Wv, const float* bv,
              const float* zg, const float* zb, const float* sg, const float* sb,
              const float* ng, const float* nb,
              const float* pzbuf, const float* psbuf, int LP)
{
    __shared__ float xs[2][512];   // up to 8 rows x 64, P and S
    __shared__ float zb2[2][512];
    __shared__ float vb2[2][512];
    __shared__ float bufA[4096];
    __shared__ float bufB[4096];
    __shared__ float zl[64];
    __shared__ float redA[16], redB[16];

    int tid = threadIdx.x, b = blockIdx.x;
    int p = tid & 63, d0 = (tid >> 6) * 16;

    if (b == 0 && tid == 0){ g_acc[0] = 0.0; g_acc[1] = 0.0; }

    // zero then load P/S rows (coalesced); rows >= LP stay zero
    for (int i = tid; i < 512; i += 256){ xs[0][i] = 0.f; xs[1][i] = 0.f; }
    for (int i = tid; i < LP*64; i += 256){
        xs[0][i] = Pm[b*LP*64 + i];
        xs[1][i] = Sm[b*LP*64 + i];
    }
    __syncthreads();

    // barrier-free GEMV: thread -> (pass, dtype z/v, col). 8 rows per thread.
    {
        int pass = tid >> 7, dt = (tid >> 6) & 1, col = tid & 63;
        const float* W  = dt ? Wv : Wk;
        float bb = dt ? bv[col] : bk[col];
        float acc8[8];
        #pragma unroll
        for (int l = 0; l < 8; l++) acc8[l] = bb;
        #pragma unroll 4
        for (int k = 0; k < 64; k++){
            float w = W[k*64 + col];
            #pragma unroll
            for (int l = 0; l < 8; l++) acc8[l] += xs[pass][l*64 + k] * w;
        }
        if (dt == 0){
            #pragma unroll
            for (int l = 0; l < 8; l++) zb2[pass][l*64 + col] = eluf(acc8[l]);
        } else {
            #pragma unroll
            for (int l = 0; l < 8; l++) vb2[pass][l*64 + col] = acc8[l];
        }
    }
    __syncthreads();

    // chunk sums of outer products + z sums for both passes
    float accP[16], accS[16];
    #pragma unroll
    for (int i = 0; i < 16; i++){ accP[i] = 0.f; accS[i] = 0.f; }
    for (int l = 0; l < LP; l++){
        float vvP = vb2[0][l*64 + p], vvS = vb2[1][l*64 + p];
        #pragma unroll
        for (int i = 0; i < 16; i++){
            accP[i] += zb2[0][l*64 + d0 + i] * vvP;
            accS[i] += zb2[1][l*64 + d0 + i] * vvS;
        }
    }
    float zsP = 0.f, zsS = 0.f;
    if (tid < 64){
        for (int l = 0; l < LP; l++){ zsP += zb2[0][l*64 + tid]; zsS += zb2[1][l*64 + tid]; }
    }

    float rv[2], out2[2];
    // z LN, pass P -> g_Pz
    rv[0] = (tid < 64) ? zsP : 0.f; rv[1] = (tid < 64) ? zsP*zsP : 0.f;
    block_reduce_b<2>(rv, redA, out2);
    {
        float mz = out2[0]*(1.f/64.f);
        float ivz = rsqrtf(out2[1]*(1.f/64.f) - mz*mz + LN_EPS);
        if (tid < 64) g_Pz[b*64 + tid] = (zsP - mz)*ivz*zg[tid] + zb[tid];
    }
    // z LN, pass S -> zl
    rv[0] = (tid < 64) ? zsS : 0.f; rv[1] = (tid < 64) ? zsS*zsS : 0.f;
    block_reduce_b<2>(rv, redB, out2);
    {
        float mz = out2[0]*(1.f/64.f);
        float ivz = rsqrtf(out2[1]*(1.f/64.f) - mz*mz + LN_EPS);
        if (tid < 64) zl[tid] = (zsS - mz)*ivz*zg[tid] + zb[tid];
    }
    // s LN, pass P -> bufA
    float sv[2];
    sv[0] = 0.f; sv[1] = 0.f;
    #pragma unroll
    for (int i = 0; i < 16; i++){ sv[0] += accP[i]; sv[1] += accP[i]*accP[i]; }
    block_reduce_b<2>(sv, redA, out2);
    {
        float ms = out2[0]*(1.f/4096.f);
        float ivs = rsqrtf(out2[1]*(1.f/4096.f) - ms*ms + LN_EPS);
        #pragma unroll
        for (int i = 0; i < 16; i++){
            int e = (d0 + i)*64 + p;
            bufA[e] = (accP[i] - ms)*ivs*sg[e] + sb[e];
        }
    }
    // s LN, pass S -> bufB
    sv[0] = 0.f; sv[1] = 0.f;
    #pragma unroll
    for (int i = 0; i < 16; i++){ sv[0] += accS[i]; sv[1] += accS[i]*accS[i]; }
    block_reduce_b<2>(sv, redB, out2);
    {
        float ms = out2[0]*(1.f/4096.f);
        float ivs = rsqrtf(out2[1]*(1.f/4096.f) - ms*ms + LN_EPS);
        #pragma unroll
        for (int i = 0; i < 16; i++){
            int e = (d0 + i)*64 + p;
            bufB[e] = (accS[i] - ms)*ivs*sg[e] + sb[e];
        }
    }
    __syncthreads();   // bufA/bufB/zl visible to all

    // history path
    int u = uid[b];
    float pzv = 0.f;
    if (tid < 64) pzv = pzbuf[(size_t)u*64 + tid] + zl[tid];
    float rv1[1], out1[1];
    rv1[0] = (tid < 64) ? pzv*pzv : 0.f;
    block_reduce_b<1>(rv1, redA, out1);
    float ipn = 1.f / (fmaxf(sqrtf(out1[0]), 1e-8f) + EPS);

    float pn16[16];
    sv[0] = 0.f; sv[1] = 0.f;
    #pragma unroll
    for (int k2 = 0; k2 < 16; k2++){
        int e = tid + k2*256;
        float pv = (psbuf[(size_t)u*4096 + e] + bufB[e]) * ipn;
        pn16[k2] = pv; sv[0] += pv; sv[1] += pv*pv;
    }
    block_reduce_b<2>(sv, redB, out2);
    float mp = out2[0]*(1.f/4096.f);
    float ivp = rsqrtf(out2[1]*(1.f/4096.f) - mp*mp + LN_EPS);
    #pragma unroll
    for (int k2 = 0; k2 < 16; k2++){
        int e = tid + k2*256;
        float M = (pn16[k2] - mp)*ivp*ng[e] + nb[e];
        g_pack[b*4096 + e] = make_float4(sg[e], sb[e] + bufA[e], ng[e], nb[e] + M);
    }
}

// ---------------- kernel B: barrier-free q/z/v GEMMs + per-chunk partial sums ----------------
__global__ __launch_bounds__(256)
void k_phase1(const float* X, const float* Wq, const float* bq,
              const float* Wk, const float* bk, const float* Wv, const float* bv,
              int NCH)
{
    __shared__ float xsT[64*36];     // transposed X chunk: [k][l], pitch 36 (16B aligned)
    __shared__ float zbuf[32*64];
    __shared__ float vbuf[32*64];

    int tid = threadIdx.x;
    int b = blockIdx.x / NCH, ch = blockIdx.x % NCH;
    int L = NCH * CHUNK;
    size_t xbase = ((size_t)b*L + (size_t)ch*CHUNK) * 64;

    // load + transpose X chunk (coalesced global reads)
    #pragma unroll
    for (int i = 0; i < 8; i++){
        int e = tid + i*256;
        int l = e >> 6, k = e & 63;
        xsT[k*36 + l] = X[xbase + e];
    }
    __syncthreads();

    // one thread = one output column of q/z/v for all 32 rows
    if (tid < 192){
        int dt = tid >> 6, col = tid & 63;
        const float* W = (dt == 0) ? Wq : ((dt == 1) ? Wk : Wv);
        float bb = (dt == 0) ? bq[col] : ((dt == 1) ? bk[col] : bv[col]);
        float acc32[32];
        #pragma unroll
        for (int l = 0; l < 32; l++) acc32[l] = bb;
        #pragma unroll 4
        for (int k = 0; k < 64; k++){
            float w = W[k*64 + col];
            const float4* xr = (const float4*)&xsT[k*36];
            #pragma unroll
            for (int lv = 0; lv < 8; lv++){
                float4 x4 = xr[lv];
                acc32[lv*4+0] += x4.x * w;
                acc32[lv*4+1] += x4.y * w;
                acc32[lv*4+2] += x4.z * w;
                acc32[lv*4+3] += x4.w * w;
            }
        }
        if (dt == 0){
            #pragma unroll
            for (int l = 0; l < 32; l++) g_q[xbase + l*64 + col] = eluf(acc32[l]);
        } else if (dt == 1){
            #pragma unroll
            for (int l = 0; l < 32; l++){
                float zv = eluf(acc32[l]);
                zbuf[l*64 + col] = zv;
                g_z[xbase + l*64 + col] = zv;
            }
        } else {
            #pragma unroll
            for (int l = 0; l < 32; l++){
                vbuf[l*64 + col] = acc32[l];
                g_v[xbase + l*64 + col] = acc32[l];
            }
        }
    }
    __syncthreads();

    // chunk-total outer products + z sums
    int p = tid & 63, d0 = (tid >> 6) * 16;
    float acc[16];
    #pragma unroll
    for (int i = 0; i < 16; i++) acc[i] = 0.f;
    #pragma unroll 4
    for (int l = 0; l < 32; l++){
        float vv = vbuf[l*64 + p];
        #pragma unroll
        for (int i = 0; i < 16; i++) acc[i] += zbuf[l*64 + d0 + i] * vv;
    }
    size_t o = (size_t)(b*NCH + ch) * 4160;
    #pragma unroll
    for (int i = 0; i < 16; i++) g_part[o + (d0 + i)*64 + p] = acc[i];
    if (tid < 64){
        float zs = 0.f;
        #pragma unroll 4
        for (int l = 0; l < 32; l++) zs += zbuf[l*64 + tid];
        g_part[o + 4096 + tid] = zs;
    }
}

// ---------------- kernel C: exclusive prefix of chunk partials per batch ----------------
__global__ __launch_bounds__(256)
void k_prefix(int NCH)
{
    int b = blockIdx.x, tid = threadIdx.x;
    float run[17];
    #pragma unroll
    for (int k = 0; k < 17; k++) run[k] = 0.f;
    for (int ch = 0; ch < NCH; ch++){
        size_t o = (size_t)(b*NCH + ch) * 4160;
        #pragma unroll
        for (int k = 0; k < 17; k++){
            int e = tid + k*256;
            if (e < 4160){ g_base[o + e] = run[k]; run[k] += g_part[o + e]; }
        }
    }
}

// ---------------- kernel D: main per-step scan (pack in registers, 5 syncs/step) ----------------
__global__ __launch_bounds__(256, 2)
void k_main(const float* zg, const float* zb, const float* nag, const float* nab,
            float* out, int NCH)
{
    __shared__ float zst[64], vst[64], qst[64];
    __shared__ float zpx[64], zpy[64], nagz[64], nabz[64];
    __shared__ float na_part[256];
    __shared__ float redA[40], redB[24], redC[4];
    __shared__ double db[128];

    int tid = threadIdx.x;
    int b = blockIdx.x / NCH, ch = blockIdx.x % NCH;
    int p = tid & 63, d0 = (tid >> 6) * 16;
    int L = NCH * CHUNK;
    size_t base = ((size_t)b*L + (size_t)ch*CHUNK) * 64;

    // packed constants -> registers (read once; eliminates 512B/thread/step smem traffic)
    float wx[16], wy[16], wz[16], ww[16];
    {
        const float4* pk = &g_pack[b*4096];
        #pragma unroll
        for (int i = 0; i < 16; i++){
            float4 w = pk[(d0 + i)*64 + p];
            wx[i] = w.x; wy[i] = w.y; wz[i] = w.z; ww[i] = w.w;
        }
    }
    if (tid < 64){
        zpx[tid]  = zg[tid];
        zpy[tid]  = zb[tid] + g_Pz[b*64 + tid];
        nagz[tid] = nag[tid];
        nabz[tid] = nab[tid];
    }
    float A[16];
    size_t ob = (size_t)(b*NCH + ch) * 4160;
    #pragma unroll
    for (int i = 0; i < 16; i++) A[i] = g_base[ob + (d0 + i)*64 + p];
    float zc = (tid < 64) ? g_base[ob + 4096 + tid] : 0.f;
    double dsum = 0.0, dsq = 0.0;

    // prefetch step 0
    float nxt = 0.f;
    if (tid < 64)        nxt = g_z[base + tid];
    else if (tid < 128)  nxt = g_v[base + (tid - 64)];
    else if (tid < 192)  nxt = g_q[base + (tid - 128)];

    for (int r = 0; r < CHUNK; r++){
        // publish current step's z/v/q
        if (tid < 64)        zst[tid]       = nxt;
        else if (tid < 128)  vst[tid - 64]  = nxt;
        else if (tid < 192)  qst[tid - 128] = nxt;
        __syncthreads();                                   // sync 1

        // prefetch next step (clamped)
        int rn = (r + 1 < CHUNK) ? (r + 1) : (CHUNK - 1);
        size_t idx2 = base + (size_t)rn * 64;
        if (tid < 64)        nxt = g_z[idx2 + tid];
        else if (tid < 128)  nxt = g_v[idx2 + (tid - 64)];
        else if (tid < 192)  nxt = g_q[idx2 + (tid - 128)];

        // state update + stats
        float vv = vst[p];
        float rv[5], o1[5];
        rv[0] = 0.f; rv[1] = 0.f;
        #pragma unroll
        for (int i = 0; i < 16; i++){
            A[i] += zst[d0 + i] * vv;
            rv[0] += A[i]; rv[1] += A[i]*A[i];
        }
        if (tid < 64){
            zc += zst[tid];
            float qv = qst[tid];
            rv[2] = zc; rv[3] = zc*zc; rv[4] = qv*qv;
        } else { rv[2] = 0.f; rv[3] = 0.f; rv[4] = 0.f; }
        block_reduce_b<5>(rv, redA, o1);                   // sync 2
        float aBar = o1[0]*(1.f/4096.f);
        float ivs  = rsqrtf(o1[1]*(1.f/4096.f) - aBar*aBar + LN_EPS);
        float mzv  = o1[2]*(1.f/64.f);
        float ivz  = rsqrtf(o1[3]*(1.f/64.f) - mzv*mzv + LN_EPS);
        float srq  = 1.f / fmaxf(sqrtf(o1[4]), 1e-8f);

        // st stats (+ zt stats, std accumulation)
        float sv[3], o2[3];
        sv[0] = 0.f; sv[1] = 0.f; sv[2] = 0.f;
        #pragma unroll
        for (int i = 0; i < 16; i++){
            float st = (A[i] - aBar)*ivs*wx[i] + wy[i];
            sv[0] += st; sv[1] += st*st;
        }
        if (tid < 64){
            float zt = (zc - mzv)*ivz*zpx[tid] + zpy[tid];
            sv[2] = zt*zt;
            float rr = qst[tid] / fmaxf(zt, 1e-6f);
            dsum += (double)rr; dsq += (double)rr * (double)rr;
        }
        block_reduce_b<3>(sv, redB, o2);                   // sync 3
        float zn   = fmaxf(sqrtf(o2[2]), 1e-8f);
        float izn  = 1.f / zn;
        float mst  = o2[0]*(1.f/4096.f);
        float mnam = mst * izn;
        float vnam = (o2[1]*(1.f/4096.f) - mst*mst) * izn * izn;
        float ivn  = rsqrtf(vnam + LN_EPS);
        float k1   = izn * ivn, k0 = -mnam * ivn;

        // na contraction
        float accn = 0.f;
        #pragma unroll
        for (int i = 0; i < 16; i++){
            float st = (A[i] - aBar)*ivs*wx[i] + wy[i];
            float a  = st*k1 + k0;
            accn += qst[d0 + i] * (a*wz[i] + ww[i]);
        }
        na_part[tid] = accn;
        __syncthreads();                                   // sync 4

        float nv = 0.f;
        if (tid < 64){
            nv = (na_part[tid] + na_part[tid+64] + na_part[tid+128] + na_part[tid+192]) * srq;
            float s1 = nv, s2 = nv*nv;
            #pragma unroll
            for (int o = 16; o; o >>= 1){
                s1 += __shfl_xor_sync(0xffffffffu, s1, o);
                s2 += __shfl_xor_sync(0xffffffffu, s2, o);
            }
            if ((tid & 31) == 0){ redC[(tid>>5)*2] = s1; redC[(tid>>5)*2 + 1] = s2; }
        }
        __syncthreads();                                   // sync 5
        if (tid < 64){
            float S1 = redC[0] + redC[2], S2 = redC[1] + redC[3];
            float mn = S1*(1.f/64.f);
            float iv = rsqrtf(S2*(1.f/64.f) - mn*mn + LN_EPS);
            out[base + (size_t)r*64 + tid] = (nv - mn)*iv*nagz[tid] + nabz[tid];
        }
    }

    // reduce local double sums -> global
    __syncthreads();
    if (tid < 64){ db[tid] = dsum; db[64 + tid] = dsq; }
    __syncthreads();
    if (tid == 0){
        double a = 0.0, c = 0.0;
        for (int i = 0; i < 64; i++){ a += db[i]; c += db[64 + i]; }
        atomicAdd(&g_acc[0], a);
        atomicAdd(&g_acc[1], c);
    }
}

// ---------------- kernel E: finalize std ----------------
__global__ void k_std(float* out, int n, int outpos)
{
    double mean = g_acc[0] / (double)n;
    double var  = (g_acc[1] - g_acc[0]*mean) / (double)(n - 1);
    out[outpos] = (float)sqrt(var);
}

// ---------------- launch ----------------
extern "C" void kernel_launch(void* const* d_in, const int* in_sizes, int n_in,
                              void* d_out, int out_size)
{
    const int*   uid   = (const int*)  d_in[0];
    const float* X     = (const float*)d_in[1];
    const float* Pm    = (const float*)d_in[2];
    const float* Sm    = (const float*)d_in[3];
    const float* Wq    = (const float*)d_in[4];
    const float* bq    = (const float*)d_in[5];
    const float* Wk    = (const float*)d_in[6];
    const float* bk    = (const float*)d_in[7];
    const float* Wv    = (const float*)d_in[8];
    const float* bv    = (const float*)d_in[9];
    const float* zg    = (const float*)d_in[10];
    const float* zb    = (const float*)d_in[11];
    const float* sg    = (const float*)d_in[12];
    const float* sb    = (const float*)d_in[13];
    const float* ng    = (const float*)d_in[14];
    const float* nb    = (const float*)d_in[15];
    const float* nag   = (const float*)d_in[16];
    const float* nab   = (const float*)d_in[17];
    const float* pzbuf = (const float*)d_in[18];
    const float* psbuf = (const float*)d_in[19];
    float* out = (float*)d_out;

    int B   = in_sizes[0];
    int L   = in_sizes[1] / (B * 64);
    int NCH = L / CHUNK;
    int LP  = in_sizes[2] / (B * 64);

    k_prompt<<<B, 256>>>(uid, Pm, Sm, Wk, bk, Wv, bv, zg, zb, sg, sb, ng, nb,
                         pzbuf, psbuf, LP);
    k_phase1<<<B*NCH, 256>>>(X, Wq, bq, Wk, bk, Wv, bv, NCH);
    k_prefix<<<B, 256>>>(NCH);
    k_main<<<B*NCH, 256>>>(zg, zb, nag, nab, out, NCH);
    k_std<<<1, 1>>>(out, B*L*64, out_size - 1);
}

// round 8
// speedup vs baseline: 1.9476x; 1.3517x over previous
#include <cuda_runtime.h>
#include <math.h>

#define EPS 1e-8f
#define LN_EPS 1e-5f
#define CHUNK 32

// ---------------- scratch (static __device__, no allocs) ----------------
__device__ __align__(16) float  g_q[16*512*64];
__device__ __align__(16) float  g_z[16*512*64];
__device__ __align__(16) float  g_v[16*512*64];
__device__ __align__(16) float  g_part[16*16*4160];
__device__ float4 g_pack[16*4096];      // {sg, sb+Ps_ln, ng, nb+Mprev_ln}
__device__ float  g_Pz[16*64];          // P_z_ln last step per batch
__device__ double g_acc[2];             // sum, sumsq for std

__device__ __forceinline__ float eluf(float x){ return x > 0.f ? x : (expf(x) - 1.f); }

// one-sync block reduce for 256 threads (8 warps). Results broadcast to ALL
// threads in out[]. red: >= 8*N floats; must not be rewritten until a
// block-wide sync after return (alternate buffers for back-to-back calls).
template<int N>
__device__ __forceinline__ void block_reduce_b(const float* v, float* red, float* out){
    int lane = threadIdx.x & 31, w = threadIdx.x >> 5;
    #pragma unroll
    for (int i = 0; i < N; i++){
        float x = v[i];
        #pragma unroll
        for (int o = 16; o; o >>= 1) x += __shfl_xor_sync(0xffffffffu, x, o);
        if (lane == 0) red[w*N + i] = x;
    }
    __syncthreads();
    #pragma unroll
    for (int i = 0; i < N; i++){
        float s = 0.f;
        #pragma unroll
        for (int ww2 = 0; ww2 < 8; ww2++) s += red[ww2*N + i];
        out[i] = s;
    }
}

// ---------------- fused front kernel: phase1 GEMMs (blocks [0,B*NCH)) +
// ---------------- prompt/history precompute (blocks [B*NCH, B*NCH+B)) ----
__global__ __launch_bounds__(256)
void k_front(const int* uid, const float* X, const float* Pm, const float* Sm,
             const float* Wq, const float* bq, const float* Wk, const float* bk,
             const float* Wv, const float* bv,
             const float* zg, const float* zb, const float* sg, const float* sb,
             const float* ng, const float* nb,
             const float* pzbuf, const float* psbuf, int NCH, int LP, int NPH)
{
    __shared__ __align__(16) float SBUF[11360];
    int tid = threadIdx.x;

    if ((int)blockIdx.x < NPH){
        // ---------------- phase1 branch ----------------
        float* xsT  = SBUF;            // 64*36 transposed X chunk
        float* zbuf = SBUF + 2304;     // 32*64
        float* vbuf = SBUF + 4352;     // 32*64

        int b = blockIdx.x / NCH, ch = blockIdx.x % NCH;
        int L = NCH * CHUNK;
        size_t xbase = ((size_t)b*L + (size_t)ch*CHUNK) * 64;

        #pragma unroll
        for (int i = 0; i < 8; i++){
            int e = tid + i*256;
            int l = e >> 6, k = e & 63;
            xsT[k*36 + l] = X[xbase + e];
        }
        __syncthreads();

        if (tid < 192){
            int dt = tid >> 6, col = tid & 63;
            const float* W = (dt == 0) ? Wq : ((dt == 1) ? Wk : Wv);
            float bb = (dt == 0) ? bq[col] : ((dt == 1) ? bk[col] : bv[col]);
            float acc32[32];
            #pragma unroll
            for (int l = 0; l < 32; l++) acc32[l] = bb;
            #pragma unroll 4
            for (int k = 0; k < 64; k++){
                float w = W[k*64 + col];
                const float4* xr = (const float4*)&xsT[k*36];
                #pragma unroll
                for (int lv = 0; lv < 8; lv++){
                    float4 x4 = xr[lv];
                    acc32[lv*4+0] += x4.x * w;
                    acc32[lv*4+1] += x4.y * w;
                    acc32[lv*4+2] += x4.z * w;
                    acc32[lv*4+3] += x4.w * w;
                }
            }
            if (dt == 0){
                #pragma unroll
                for (int l = 0; l < 32; l++) g_q[xbase + l*64 + col] = eluf(acc32[l]);
            } else if (dt == 1){
                #pragma unroll
                for (int l = 0; l < 32; l++){
                    float zv = eluf(acc32[l]);
                    zbuf[l*64 + col] = zv;
                    g_z[xbase + l*64 + col] = zv;
                }
            } else {
                #pragma unroll
                for (int l = 0; l < 32; l++){
                    vbuf[l*64 + col] = acc32[l];
                    g_v[xbase + l*64 + col] = acc32[l];
                }
            }
        }
        __syncthreads();

        int p = tid & 63, d0 = (tid >> 6) * 16;
        float acc[16];
        #pragma unroll
        for (int i = 0; i < 16; i++) acc[i] = 0.f;
        #pragma unroll 4
        for (int l = 0; l < 32; l++){
            float vv = vbuf[l*64 + p];
            #pragma unroll
            for (int i = 0; i < 16; i++) acc[i] += zbuf[l*64 + d0 + i] * vv;
        }
        size_t o = (size_t)(b*NCH + ch) * 4160;
        #pragma unroll
        for (int i = 0; i < 16; i++) g_part[o + (d0 + i)*64 + p] = acc[i];
        if (tid < 64){
            float zs = 0.f;
            #pragma unroll 4
            for (int l = 0; l < 32; l++) zs += zbuf[l*64 + tid];
            g_part[o + 4096 + tid] = zs;
        }
        return;
    }

    // ---------------- prompt branch ----------------
    float* xsA  = SBUF;          float* xsB  = SBUF + 512;
    float* zbA  = SBUF + 1024;   float* zbB  = SBUF + 1536;
    float* vbA  = SBUF + 2048;   float* vbB  = SBUF + 2560;
    float* bufA = SBUF + 3072;   float* bufB = SBUF + 7168;
    float* zl   = SBUF + 11264;
    float* redA = SBUF + 11328;  float* redB = SBUF + 11344;

    int b = blockIdx.x - NPH;
    int p = tid & 63, d0 = (tid >> 6) * 16;

    if (b == 0 && tid == 0){ g_acc[0] = 0.0; g_acc[1] = 0.0; }

    for (int i = tid; i < 512; i += 256){ xsA[i] = 0.f; xsB[i] = 0.f; }
    for (int i = tid; i < LP*64; i += 256){
        xsA[i] = Pm[b*LP*64 + i];
        xsB[i] = Sm[b*LP*64 + i];
    }
    __syncthreads();

    {
        int pass = tid >> 7, dt = (tid >> 6) & 1, col = tid & 63;
        const float* xp = pass ? xsB : xsA;
        float* zp = pass ? zbB : zbA;
        float* vp = pass ? vbB : vbA;
        const float* W  = dt ? Wv : Wk;
        float bb = dt ? bv[col] : bk[col];
        float acc8[8];
        #pragma unroll
        for (int l = 0; l < 8; l++) acc8[l] = bb;
        #pragma unroll 4
        for (int k = 0; k < 64; k++){
            float w = W[k*64 + col];
            #pragma unroll
            for (int l = 0; l < 8; l++) acc8[l] += xp[l*64 + k] * w;
        }
        if (dt == 0){
            #pragma unroll
            for (int l = 0; l < 8; l++) zp[l*64 + col] = eluf(acc8[l]);
        } else {
            #pragma unroll
            for (int l = 0; l < 8; l++) vp[l*64 + col] = acc8[l];
        }
    }
    __syncthreads();

    float accP[16], accS[16];
    #pragma unroll
    for (int i = 0; i < 16; i++){ accP[i] = 0.f; accS[i] = 0.f; }
    for (int l = 0; l < LP; l++){
        float vvP = vbA[l*64 + p], vvS = vbB[l*64 + p];
        #pragma unroll
        for (int i = 0; i < 16; i++){
            accP[i] += zbA[l*64 + d0 + i] * vvP;
            accS[i] += zbB[l*64 + d0 + i] * vvS;
        }
    }
    float zsP = 0.f, zsS = 0.f;
    if (tid < 64){
        for (int l = 0; l < LP; l++){ zsP += zbA[l*64 + tid]; zsS += zbB[l*64 + tid]; }
    }

    float rv[2], out2[2];
    rv[0] = (tid < 64) ? zsP : 0.f; rv[1] = (tid < 64) ? zsP*zsP : 0.f;
    block_reduce_b<2>(rv, redA, out2);
    {
        float mz = out2[0]*(1.f/64.f);
        float ivz = rsqrtf(out2[1]*(1.f/64.f) - mz*mz + LN_EPS);
        if (tid < 64) g_Pz[b*64 + tid] = (zsP - mz)*ivz*zg[tid] + zb[tid];
    }
    rv[0] = (tid < 64) ? zsS : 0.f; rv[1] = (tid < 64) ? zsS*zsS : 0.f;
    block_reduce_b<2>(rv, redB, out2);
    {
        float mz = out2[0]*(1.f/64.f);
        float ivz = rsqrtf(out2[1]*(1.f/64.f) - mz*mz + LN_EPS);
        if (tid < 64) zl[tid] = (zsS - mz)*ivz*zg[tid] + zb[tid];
    }
    float sv[2];
    sv[0] = 0.f; sv[1] = 0.f;
    #pragma unroll
    for (int i = 0; i < 16; i++){ sv[0] += accP[i]; sv[1] += accP[i]*accP[i]; }
    block_reduce_b<2>(sv, redA, out2);
    {
        float ms = out2[0]*(1.f/4096.f);
        float ivs = rsqrtf(out2[1]*(1.f/4096.f) - ms*ms + LN_EPS);
        #pragma unroll
        for (int i = 0; i < 16; i++){
            int e = (d0 + i)*64 + p;
            bufA[e] = (accP[i] - ms)*ivs*sg[e] + sb[e];
        }
    }
    sv[0] = 0.f; sv[1] = 0.f;
    #pragma unroll
    for (int i = 0; i < 16; i++){ sv[0] += accS[i]; sv[1] += accS[i]*accS[i]; }
    block_reduce_b<2>(sv, redB, out2);
    {
        float ms = out2[0]*(1.f/4096.f);
        float ivs = rsqrtf(out2[1]*(1.f/4096.f) - ms*ms + LN_EPS);
        #pragma unroll
        for (int i = 0; i < 16; i++){
            int e = (d0 + i)*64 + p;
            bufB[e] = (accS[i] - ms)*ivs*sg[e] + sb[e];
        }
    }
    __syncthreads();

    int u = uid[b];
    float pzv = 0.f;
    if (tid < 64) pzv = pzbuf[(size_t)u*64 + tid] + zl[tid];
    float rv1[1], out1[1];
    rv1[0] = (tid < 64) ? pzv*pzv : 0.f;
    block_reduce_b<1>(rv1, redA, out1);
    float ipn = 1.f / (fmaxf(sqrtf(out1[0]), 1e-8f) + EPS);

    float pn16[16];
    sv[0] = 0.f; sv[1] = 0.f;
    #pragma unroll
    for (int k2 = 0; k2 < 16; k2++){
        int e = tid + k2*256;
        float pv = (psbuf[(size_t)u*4096 + e] + bufB[e]) * ipn;
        pn16[k2] = pv; sv[0] += pv; sv[1] += pv*pv;
    }
    block_reduce_b<2>(sv, redB, out2);
    float mp = out2[0]*(1.f/4096.f);
    float ivp = rsqrtf(out2[1]*(1.f/4096.f) - mp*mp + LN_EPS);
    #pragma unroll
    for (int k2 = 0; k2 < 16; k2++){
        int e = tid + k2*256;
        float M = (pn16[k2] - mp)*ivp*ng[e] + nb[e];
        g_pack[b*4096 + e] = make_float4(sg[e], sb[e] + bufA[e], ng[e], nb[e] + M);
    }
}

// ---------------- kernel D: main per-step scan (tiles preloaded, fused prefix,
// ---------------- single merged 12-wide reduce, warp0 epilogue: 2 syncs/step) --
__global__ __launch_bounds__(256, 2)
void k_main(const float* __restrict__ zg, const float* __restrict__ zb,
            const float* __restrict__ nag, const float* __restrict__ nab,
            float* __restrict__ out, int NCH)
{
    __shared__ __align__(16) float ztile[2048];
    __shared__ __align__(16) float vtile[2048];
    __shared__ __align__(16) float qtile[2048];
    __shared__ float4 red4[8][3];
    __shared__ float na_part[256];
    __shared__ float cred[64];
    __shared__ double db[128];

    int tid = threadIdx.x;
    int b = blockIdx.x / NCH, ch = blockIdx.x % NCH;
    int lane = tid & 31, w = tid >> 5;
    int p = tid & 63, d0 = (tid >> 6) * 16;
    int L = NCH * CHUNK;
    size_t base = ((size_t)b*L + (size_t)ch*CHUNK) * 64;

    // preload whole chunk z/v/q tiles (float4)
    {
        const float4* gz4 = (const float4*)(g_z + base);
        const float4* gv4 = (const float4*)(g_v + base);
        const float4* gq4 = (const float4*)(g_q + base);
        float4* zt4 = (float4*)ztile; float4* vt4 = (float4*)vtile; float4* qt4 = (float4*)qtile;
        #pragma unroll
        for (int i = 0; i < 2; i++){
            int e = tid + i*256;
            zt4[e] = gz4[e]; vt4[e] = gv4[e]; qt4[e] = gq4[e];
        }
    }
    // packed constants -> registers
    float wx[16], wy[16], wz[16], ww[16];
    {
        const float4* pk = &g_pack[b*4096];
        #pragma unroll
        for (int i = 0; i < 16; i++){
            float4 t = pk[(d0 + i)*64 + p];
            wx[i] = t.x; wy[i] = t.y; wz[i] = t.z; ww[i] = t.w;
        }
    }
    float zpxv = 0.f, zpyv = 0.f;
    if (tid < 64){ zpxv = zg[tid]; zpyv = zb[tid] + g_Pz[b*64 + tid]; }
    float ngA = 0.f, ngB = 0.f, nbA = 0.f, nbB = 0.f;
    if (tid < 32){ ngA = nag[lane]; ngB = nag[lane+32]; nbA = nab[lane]; nbB = nab[lane+32]; }

    // fused exclusive prefix over prior chunks' partials
    float A[16];
    #pragma unroll
    for (int i = 0; i < 16; i++) A[i] = 0.f;
    float zc = 0.f;
    for (int c2 = 0; c2 < ch; c2++){
        const float* gp = &g_part[(size_t)(b*NCH + c2) * 4160];
        #pragma unroll
        for (int i = 0; i < 16; i++) A[i] += gp[(d0 + i)*64 + p];
        if (tid < 64) zc += gp[4096 + tid];
    }

    // per-CTA constants (one 8-wide block reduce; also makes tiles visible)
    float Cwx, Cwx2, Cwxwy, Cwy, Cwy2, Czpx2, Czpxzpy, Czpy2;
    {
        float cv[8];
        cv[0]=cv[1]=cv[2]=cv[3]=cv[4]=0.f;
        #pragma unroll
        for (int i = 0; i < 16; i++){
            cv[0] += wx[i];       cv[1] = fmaf(wx[i], wx[i], cv[1]);
            cv[2] = fmaf(wx[i], wy[i], cv[2]);
            cv[3] += wy[i];       cv[4] = fmaf(wy[i], wy[i], cv[4]);
        }
        cv[5] = zpxv*zpxv; cv[6] = zpxv*zpyv; cv[7] = zpyv*zpyv;  // 0 for tid>=64
        #pragma unroll
        for (int k = 0; k < 8; k++){
            #pragma unroll
            for (int o = 16; o; o >>= 1) cv[k] += __shfl_xor_sync(0xffffffffu, cv[k], o);
        }
        if (lane == 0){
            #pragma unroll
            for (int k = 0; k < 8; k++) cred[w*8 + k] = cv[k];
        }
        __syncthreads();
        float s[8];
        #pragma unroll
        for (int k = 0; k < 8; k++){
            float t = 0.f;
            #pragma unroll
            for (int w2 = 0; w2 < 8; w2++) t += cred[w2*8 + k];
            s[k] = t;
        }
        Cwx=s[0]; Cwx2=s[1]; Cwxwy=s[2]; Cwy=s[3]; Cwy2=s[4];
        Czpx2=s[5]; Czpxzpy=s[6]; Czpy2=s[7];
    }
    double dsum = 0.0, dsq = 0.0;
    const float inv4096 = 1.f/4096.f, inv64 = 1.f/64.f;

    #pragma unroll 1
    for (int r = 0; r < CHUNK; r++){
        const float* zr = &ztile[r*64];
        float vv = vtile[r*64 + p];
        float sA = 0.f, sA2 = 0.f, sU = 0.f, sU2 = 0.f, sUwx = 0.f, sUwy = 0.f;
        #pragma unroll
        for (int i = 0; i < 16; i++){
            A[i] = fmaf(zr[d0 + i], vv, A[i]);
            float a = A[i];
            sA += a; sA2 = fmaf(a, a, sA2);
            float uu = a * wx[i];
            sU += uu; sU2 = fmaf(uu, uu, sU2);
            sUwx = fmaf(uu, wx[i], sUwx);
            sUwy = fmaf(uu, wy[i], sUwy);
        }
        float qv = 0.f, r6 = 0.f, r7 = 0.f, r8 = 0.f, r9 = 0.f, r10 = 0.f, r11 = 0.f;
        if (tid < 64){
            zc += zr[tid];
            qv = qtile[r*64 + tid];
            float y = zc * zpxv;
            r6 = zc; r7 = zc*zc; r8 = y*y; r9 = y*zpyv; r10 = y*zpxv; r11 = qv*qv;
        }
        #pragma unroll
        for (int o = 16; o; o >>= 1){
            sA   += __shfl_xor_sync(0xffffffffu, sA, o);
            sA2  += __shfl_xor_sync(0xffffffffu, sA2, o);
            sU   += __shfl_xor_sync(0xffffffffu, sU, o);
            sU2  += __shfl_xor_sync(0xffffffffu, sU2, o);
            sUwx += __shfl_xor_sync(0xffffffffu, sUwx, o);
            sUwy += __shfl_xor_sync(0xffffffffu, sUwy, o);
        }
        if (w < 2){
            #pragma unroll
            for (int o = 16; o; o >>= 1){
                r6  += __shfl_xor_sync(0xffffffffu, r6, o);
                r7  += __shfl_xor_sync(0xffffffffu, r7, o);
                r8  += __shfl_xor_sync(0xffffffffu, r8, o);
                r9  += __shfl_xor_sync(0xffffffffu, r9, o);
                r10 += __shfl_xor_sync(0xffffffffu, r10, o);
                r11 += __shfl_xor_sync(0xffffffffu, r11, o);
            }
        }
        if (lane == 0){
            red4[w][0] = make_float4(sA, sA2, sU, sU2);
            red4[w][1] = make_float4(sUwx, sUwy, r6, r7);
            red4[w][2] = make_float4(r8, r9, r10, r11);
        }
        __syncthreads();                                       // sync 1
        float4 a0 = red4[0][0], a1 = red4[0][1], a2v = red4[0][2];
        #pragma unroll
        for (int w2 = 1; w2 < 8; w2++){
            float4 t0 = red4[w2][0], t1 = red4[w2][1], t2 = red4[w2][2];
            a0.x += t0.x; a0.y += t0.y; a0.z += t0.z; a0.w += t0.w;
            a1.x += t1.x; a1.y += t1.y; a1.z += t1.z; a1.w += t1.w;
            a2v.x += t2.x; a2v.y += t2.y; a2v.z += t2.z; a2v.w += t2.w;
        }
        // scalar closed-forms
        float aBar = a0.x * inv4096;
        float ivs  = rsqrtf(a0.y*inv4096 - aBar*aBar + LN_EPS);
        float c0   = aBar * ivs;
        float Sst  = ivs*a0.z - c0*Cwx + Cwy;
        float Sst2 = ivs*ivs*a0.w + 2.f*ivs*(a1.y - c0*a1.x)
                   + Cwy2 - 2.f*c0*Cwxwy + c0*c0*Cwx2;
        float mzv  = a1.z * inv64;
        float ivz  = rsqrtf(a1.w*inv64 - mzv*mzv + LN_EPS);
        float dd0  = mzv * ivz;
        float Szt2 = ivz*ivz*a2v.x + 2.f*ivz*(a2v.y - dd0*a2v.z)
                   + Czpy2 - 2.f*dd0*Czpxzpy + dd0*dd0*Czpx2;
        float zn   = fmaxf(sqrtf(Szt2), 1e-8f);
        float izn  = 1.f / zn;
        float mst  = Sst * inv4096;
        float mnam = mst * izn;
        float vnam = (Sst2*inv4096 - mst*mst) * izn * izn;
        float ivn  = rsqrtf(vnam + LN_EPS);
        float k1   = izn * ivn, k0 = -mnam * ivn;
        float srq  = 1.f / fmaxf(sqrtf(a2v.w), 1e-8f);

        if (tid < 64){
            float zt = (zc - mzv)*ivz*zpxv + zpyv;
            float rr = qv / fmaxf(zt, 1e-6f);
            dsum += (double)rr; dsq += (double)rr * (double)rr;
        }

        // na contraction: a2 = f1*(A*wx) + f2*wx + f3*wy + k0
        float f1 = k1 * ivs, f2 = -f1 * aBar, f3 = k1;
        const float* qr = &qtile[r*64];
        float accn = 0.f;
        #pragma unroll
        for (int i = 0; i < 16; i++){
            float uu = A[i] * wx[i];
            float aa = fmaf(f1, uu, k0);
            aa = fmaf(f2, wx[i], aa);
            aa = fmaf(f3, wy[i], aa);
            float t = fmaf(aa, wz[i], ww[i]);
            accn = fmaf(qr[d0 + i], t, accn);
        }
        na_part[tid] = accn;
        __syncthreads();                                       // sync 2

        if (tid < 32){
            float nvA = (na_part[lane] + na_part[lane+64] + na_part[lane+128] + na_part[lane+192]) * srq;
            float nvB = (na_part[lane+32] + na_part[lane+96] + na_part[lane+160] + na_part[lane+224]) * srq;
            float s1 = nvA + nvB, s2 = nvA*nvA + nvB*nvB;
            #pragma unroll
            for (int o = 16; o; o >>= 1){
                s1 += __shfl_xor_sync(0xffffffffu, s1, o);
                s2 += __shfl_xor_sync(0xffffffffu, s2, o);
            }
            float mn = s1 * inv64;
            float iv = rsqrtf(s2*inv64 - mn*mn + LN_EPS);
            float* op = out + base + (size_t)r*64;
            op[lane]      = (nvA - mn)*iv*ngA + nbA;
            op[lane + 32] = (nvB - mn)*iv*ngB + nbB;
        }
    }

    // reduce local double sums -> global
    __syncthreads();
    if (tid < 64){ db[tid] = dsum; db[64 + tid] = dsq; }
    __syncthreads();
    if (tid == 0){
        double a = 0.0, c = 0.0;
        for (int i = 0; i < 64; i++){ a += db[i]; c += db[64 + i]; }
        atomicAdd(&g_acc[0], a);
        atomicAdd(&g_acc[1], c);
    }
}

// ---------------- kernel E: finalize std ----------------
__global__ void k_std(float* out, int n, int outpos)
{
    double mean = g_acc[0] / (double)n;
    double var  = (g_acc[1] - g_acc[0]*mean) / (double)(n - 1);
    out[outpos] = (float)sqrt(var);
}

// ---------------- launch ----------------
extern "C" void kernel_launch(void* const* d_in, const int* in_sizes, int n_in,
                              void* d_out, int out_size)
{
    const int*   uid   = (const int*)  d_in[0];
    const float* X     = (const float*)d_in[1];
    const float* Pm    = (const float*)d_in[2];
    const float* Sm    = (const float*)d_in[3];
    const float* Wq    = (const float*)d_in[4];
    const float* bq    = (const float*)d_in[5];
    const float* Wk    = (const float*)d_in[6];
    const float* bk    = (const float*)d_in[7];
    const float* Wv    = (const float*)d_in[8];
    const float* bv    = (const float*)d_in[9];
    const float* zg    = (const float*)d_in[10];
    const float* zb    = (const float*)d_in[11];
    const float* sg    = (const float*)d_in[12];
    const float* sb    = (const float*)d_in[13];
    const float* ng    = (const float*)d_in[14];
    const float* nb    = (const float*)d_in[15];
    const float* nag   = (const float*)d_in[16];
    const float* nab   = (const float*)d_in[17];
    const float* pzbuf = (const float*)d_in[18];
    const float* psbuf = (const float*)d_in[19];
    float* out = (float*)d_out;

    int B   = in_sizes[0];
    int L   = in_sizes[1] / (B * 64);
    int NCH = L / CHUNK;
    int LP  = in_sizes[2] / (B * 64);
    int NPH = B * NCH;

    k_front<<<NPH + B, 256>>>(uid, X, Pm, Sm, Wq, bq, Wk, bk, Wv, bv,
                              zg, zb, sg, sb, ng, nb, pzbuf, psbuf, NCH, LP, NPH);
    k_main<<<NPH, 256>>>(zg, zb, nag, nab, out, NCH);
    k_std<<<1, 1>>>(out, B*L*64, out_size - 1);
}